// round 14
// baseline (speedup 1.0000x reference)
#include <cuda_runtime.h>
#include <cuda_fp16.h>
#include <cstdint>
#include <math.h>

#define Bb 4
#define Tt 2048
#define Cc 768
#define DKk 96
#define Nanc 8
#define NCH 64
#define LCH 32          /* Tt / NCH */
#define NSB 8
#define NT 16           /* Tt/128 */
#define MTOT (Bb*Tt)    /* 8192 */

#define KA 768          /* fp16 K */
#define BKs 32          /* K per stage */
#define TILE_BYTES (128*40*2)           /* 10240 (row stride 80B) */
#define STG_BYTES (2*TILE_BYTES)        /* A+B per stage: 20480 */
#define NSTG 4
#define SMEMSZ (NSTG*STG_BYTES + 256)   /* 82176 -> 2 CTAs/SM */

#define ATT_STRIDE_B 208                /* 104 halves per row */
#define ATT_TILE_B (128*ATT_STRIDE_B)   /* 26624 */

/* ------------ device scratch (static, no allocation) ------------- */
__device__ float d_ctxg [MTOT*Cc];
__device__ float d_cfF  [MTOT*Cc];
__device__ float d_csF  [MTOT*Cc];
__device__ float d_pm   [MTOT*NSB];
__device__ float d_cg   [MTOT];
__device__ float d_anchaF[128*Cc];
__device__ float d_delta[Bb*Cc];
__device__ float d_carG [Bb*NCH*Cc];
__device__ float d_carF [Bb*NCH*Cc];
__device__ float d_carS [Bb*NCH*Cc];

/* fp16 buffers */
__device__ __half d_xprojH[MTOT*Cc];
__device__ __half d_bfH  [MTOT*Cc];
__device__ __half d_bsH  [MTOT*Cc];
__device__ __half d_gfrH [MTOT*Cc];
__device__ __half d_gsrH [MTOT*Cc];
__device__ __half d_somarH[MTOT*Cc];
__device__ __half d_qkH  [(long)MTOT*256];
__device__ __half d_xaH  [128*KA];
__device__ __half d_xH   [(long)MTOT*KA];
__device__ __half d_ctxgH[(long)MTOT*KA];
__device__ __half d_cfH  [(long)MTOT*KA];
__device__ __half d_csH  [(long)MTOT*KA];
__device__ __half d_WpH   [768*KA];
__device__ __half d_WxfH  [768*KA];
__device__ __half d_WxsH  [768*KA];
__device__ __half d_WcfH  [768*KA];
__device__ __half d_WcsH  [768*KA];
__device__ __half d_WfastH[768*KA];
__device__ __half d_WslowH[768*KA];
__device__ __half d_WsomaH[768*KA];
__device__ __half d_WancH [768*KA];
__device__ __half d_WqkH  [256*KA];

/* ---------------- helpers ---------------- */
__device__ __forceinline__ float alpha_of(const float* tau){
    float t = *tau;
    float sp = (t > 20.f) ? t : log1pf(expf(t));
    return expf(-sp);
}
__device__ __forceinline__ float sigmoidf_(float v){ return 1.f/(1.f+expf(-v)); }

__device__ __forceinline__ uint32_t smem_u32(const void* p){
    uint32_t a;
    asm("{ .reg .u64 t; cvta.to.shared.u64 t, %1; cvt.u32.u64 %0, t; }" : "=r"(a) : "l"(p));
    return a;
}

__device__ __forceinline__ void cp_async16(uint32_t dst, const void* src){
    asm volatile("cp.async.cg.shared.global [%0], [%1], 16;" :: "r"(dst), "l"(src));
}
__device__ __forceinline__ void cp_commit(){ asm volatile("cp.async.commit_group;" ::: "memory"); }
template<int N> __device__ __forceinline__ void cp_wait(){ asm volatile("cp.async.wait_group %0;" :: "n"(N) : "memory"); }

__device__ __forceinline__ void ldm_x4(uint32_t addr, uint32_t& r0, uint32_t& r1, uint32_t& r2, uint32_t& r3){
    asm volatile("ldmatrix.sync.aligned.m8n8.x4.shared.b16 {%0,%1,%2,%3}, [%4];"
        : "=r"(r0), "=r"(r1), "=r"(r2), "=r"(r3) : "r"(addr));
}
__device__ __forceinline__ void mma16816(float& c0, float& c1, float& c2, float& c3,
                                         uint32_t a0, uint32_t a1, uint32_t a2, uint32_t a3,
                                         uint32_t b0, uint32_t b1){
    asm volatile("mma.sync.aligned.m16n8k16.row.col.f32.f16.f16.f32 "
        "{%0,%1,%2,%3}, {%4,%5,%6,%7}, {%8,%9}, {%0,%1,%2,%3};"
        : "+f"(c0), "+f"(c1), "+f"(c2), "+f"(c3)
        : "r"(a0), "r"(a1), "r"(a2), "r"(a3), "r"(b0), "r"(b1));
}

/* ---------------- fp16 conversion kernels ---------------- */
struct WConvJobs {
    const float* src[11];
    __half* dst[11];
    int nsrc[11];
    int npad[11];
};
__global__ void conv_w_all(WConvJobs J)
{
    int j = blockIdx.y;
    long i = (long)blockIdx.x*256 + threadIdx.x;
    int npad = J.npad[j];
    if (i >= (long)npad*192) return;
    int r = (int)(i / 192); int c4 = (int)(i % 192);
    float4 v = make_float4(0.f,0.f,0.f,0.f);
    if (r < J.nsrc[j]) v = *(const float4*)(J.src[j] + (long)r*768 + c4*4);
    __half2 a; a.x=__float2half(v.x); a.y=__float2half(v.y);
    __half2 b; b.x=__float2half(v.z); b.y=__float2half(v.w);
    __half2* o = (__half2*)(J.dst[j] + (long)r*KA + c4*4);
    o[0]=a; o[1]=b;
}

/* anchor gather -> fp16 rows (32 valid rows; rest of 128-row tile is zeros) */
__global__ void anchor_gather(const float* __restrict__ x, __half* __restrict__ xa)
{
    int i = blockIdx.x*256 + threadIdx.x;
    if (i >= Bb*Nanc*Cc) return;
    int c = i % Cc;
    int n = (i / Cc) % Nanc;
    int b = i / (Cc*Nanc);
    int pos = n * (Tt / Nanc);
    if (pos > Tt-1) pos = Tt-1;
    xa[i] = __float2half(x[((long)b*Tt + pos)*Cc + c]);
}

/* ---------------- ema phase-3 body (self-prefix) ---------------- */
__device__ void ema_p3_body(const float* __restrict__ h, const float* __restrict__ car,
                            const float* __restrict__ tau,
                            const float* __restrict__ cg, const float* __restrict__ delta,
                            __half* __restrict__ outH)
{
    int idx = blockIdx.x;
    if (idx >= Bb*NCH*3) return;
    int ych = idx % 3;
    int bch = idx / 3;
    int b = bch / NCH, ch = bch % NCH;
    int c = ych*256 + threadIdx.x;
    float alpha = alpha_of(tau);
    float aL = powf(alpha, (float)LCH);
    /* exclusive Horner prefix over raw chunk aggregates */
    const float* carBase = car + (long)b*NCH*Cc + c;
    float P = 0.f;
#pragma unroll 8
    for (int j = 0; j < ch; j++)
        P = fmaf(aL, P, carBase[(long)j*Cc]);
    const float* p = h + ((long)b*Tt + ch*LCH)*Cc + c;
    __half* oH = outH + ((long)b*Tt + ch*LCH)*KA + c;
    float ap = alpha;
    if (cg){
        const float* cgp = cg + (long)b*Tt + ch*LCH;
        float dl = delta[(long)b*Cc + c];
#pragma unroll 8
        for (int t=0; t<LCH; t++){
            float v = fmaf(ap, P, p[(long)t*Cc]);
            v = fmaf(v, cgp[t], dl);
            oH[(long)t*KA] = __float2half(v);
            ap *= alpha;
        }
    } else {
#pragma unroll 8
        for (int t=0; t<LCH; t++){
            float v = fmaf(ap, P, p[(long)t*Cc]);
            oH[(long)t*KA] = __float2half(v);
            ap *= alpha;
        }
    }
}

/* ---------------- batched mma.sync GEMM + co-scheduled jobs ----------
   kind 0: gemm.  kind 1: attention.  kind 2: ema phase-3 (ctx).       */
struct GemmJobs {
    const __half *A1[4], *B1[4], *A2[4], *B2[4];
    const float *bias[4];
    const __half *mult[4];
    void *out[4];
    int nseg[4], Nout[4], ncol[4], nrow[4], epi[4], kind[4];
    /* ema p3 job fields */
    const float *e_h, *e_car, *e_tau;
    __half *e_outH;
};

__device__ __forceinline__ void load_stage(const __half* __restrict__ A,
                                           const __half* __restrict__ Bp,
                                           int kofs, uint32_t sbuf, int tid)
{
    uint32_t sA = sbuf, sB = sbuf + TILE_BYTES;
#pragma unroll
    for (int it = 0; it < 2; it++){
        int ci = it*256 + tid;
        int row = ci >> 2, c = ci & 3;
        cp_async16(sA + row*80 + c*16, A + (long)row*KA + kofs + c*8);
    }
#pragma unroll
    for (int it = 0; it < 2; it++){
        int ci = it*256 + tid;
        int row = ci >> 2, c = ci & 3;
        cp_async16(sB + row*80 + c*16, Bp + (long)row*KA + kofs + c*8);
    }
    cp_commit();
}

/* attention body (flattened blockIdx.x over Bb*NT*NSB) */
__device__ void attn_body(const __half* __restrict__ qk, float* __restrict__ pm,
                          char* dynA)
{
    int idx = blockIdx.x;
    if (idx >= Bb*NT*NSB) return;
    int sb  = idx % NSB;
    int btt = idx / NSB;
    int b = btt / NT, tt = btt % NT;
    __half* qs = (__half*)dynA;
    __half* ks = (__half*)(dynA + ATT_TILE_B);
    int tid = threadIdx.x, lane = tid & 31, wid = tid >> 5;
    int wm = wid & 3, wn = wid >> 2;
    uint32_t sq = smem_u32(qs), sk = smem_u32(ks);

    const __half* qbase = qk + ((long)b*Tt + tt*128)*256;
    for (int ch = tid; ch < 128*12; ch += 256){
        int row = ch / 12, cc = ch % 12;
        cp_async16(sq + row*208 + cc*16, qbase + (long)row*256 + cc*8);
    }
    cp_commit(); cp_wait<0>(); __syncthreads();

    int aM = lane & 15, aK = (lane >> 4)*8;
    int bN = ((lane >> 4) & 1)*8 + (lane & 7), bK = ((lane >> 3) & 1)*8;

    float mreg[2][2];
    mreg[0][0]=mreg[0][1]=mreg[1][0]=mreg[1][1] = -INFINITY;

    for (int st = sb; st <= tt; st += NSB){
        const __half* kbase = qk + ((long)b*Tt + st*128)*256 + 128;
        for (int ch = tid; ch < 128*12; ch += 256){
            int row = ch / 12, cc = ch % 12;
            cp_async16(sk + row*208 + cc*16, kbase + (long)row*256 + cc*8);
        }
        cp_commit(); cp_wait<0>(); __syncthreads();

        float acc[2][8][4];
#pragma unroll
        for (int i=0;i<2;i++)
#pragma unroll
            for (int j=0;j<8;j++)
#pragma unroll
                for (int r=0;r<4;r++) acc[i][j][r]=0.f;

#pragma unroll
        for (int kk=0; kk<6; kk++){
            int k0 = kk*16;
            uint32_t a[2][4];
#pragma unroll
            for (int i=0;i<2;i++){
                uint32_t ad = sq + (uint32_t)(wm*32 + i*16 + aM)*208 + (uint32_t)(k0 + aK)*2;
                ldm_x4(ad, a[i][0], a[i][1], a[i][2], a[i][3]);
            }
            uint32_t bfr[8][2];
#pragma unroll
            for (int jj=0;jj<4;jj++){
                uint32_t bd = sk + (uint32_t)(wn*64 + jj*16 + bN)*208 + (uint32_t)(k0 + bK)*2;
                uint32_t r0,r1,r2,r3;
                ldm_x4(bd, r0, r1, r2, r3);
                bfr[2*jj][0]=r0; bfr[2*jj][1]=r1; bfr[2*jj+1][0]=r2; bfr[2*jj+1][1]=r3;
            }
#pragma unroll
            for (int i=0;i<2;i++)
#pragma unroll
                for (int j=0;j<8;j++)
                    mma16816(acc[i][j][0], acc[i][j][1], acc[i][j][2], acc[i][j][3],
                             a[i][0], a[i][1], a[i][2], a[i][3], bfr[j][0], bfr[j][1]);
        }
        __syncthreads();

        bool diag = (st == tt);
#pragma unroll
        for (int i=0;i<2;i++)
#pragma unroll
            for (int j=0;j<8;j++)
#pragma unroll
                for (int h=0;h<2;h++){
                    float v0 = acc[i][j][2*h], v1 = acc[i][j][2*h+1];
                    if (diag){
                        int row = wm*32 + i*16 + h*8 + (lane >> 2);
                        int col = wn*64 + j*8 + (lane & 3)*2;
                        if (col     > row) v0 = -INFINITY;
                        if (col + 1 > row) v1 = -INFINITY;
                    }
                    mreg[i][h] = fmaxf(mreg[i][h], fmaxf(v0, v1));
                }
    }

#pragma unroll
    for (int i=0;i<2;i++)
#pragma unroll
        for (int h=0;h<2;h++){
            float v = mreg[i][h];
            v = fmaxf(v, __shfl_xor_sync(0xffffffffu, v, 1));
            v = fmaxf(v, __shfl_xor_sync(0xffffffffu, v, 2));
            mreg[i][h] = v;
        }
    float* red = (float*)qs;
    __syncthreads();
    if ((lane & 3) == 0){
#pragma unroll
        for (int i=0;i<2;i++)
#pragma unroll
            for (int h=0;h<2;h++){
                int rowl = wm*32 + i*16 + h*8 + (lane >> 2);
                red[wn*128 + rowl] = mreg[i][h];
            }
    }
    __syncthreads();
    if (tid < 128){
        float v = fmaxf(red[tid], red[128 + tid]);
        pm[((long)b*Tt + tt*128 + tid)*NSB + sb] = v;
    }
}

__global__ void __launch_bounds__(256, 2)
mma_gemm(GemmJobs J)
{
    extern __shared__ char dyn[];
    const int jz = blockIdx.z;
    if (J.kind[jz] == 1){
        attn_body(J.A1[jz], (float*)J.out[jz], dyn);
        return;
    }
    if (J.kind[jz] == 2){
        ema_p3_body(J.e_h, J.e_car, J.e_tau, nullptr, nullptr, J.e_outH);
        return;
    }
    const int ncol = J.ncol[jz];
    const int bx = blockIdx.x;
    if (bx >= ncol * J.nrow[jz]) return;
    const int tid  = threadIdx.x;
    const int lane = tid & 31;
    const int wid  = tid >> 5;
    const int wm   = wid & 3;
    const int wn   = wid >> 2;
    const int row0 = (bx / ncol) * 128;
    const int col0 = (bx % ncol) * 128;
    const int Nout = J.Nout[jz];
    const int epi  = J.epi[jz];
    const float* bias = J.bias[jz];
    const __half* mult = J.mult[jz];
    void* out = J.out[jz];
    uint32_t sbase = (smem_u32(dyn) + 127u) & ~127u;

    const __half* Aseg[2];
    const __half* Bseg[2];
    Aseg[0] = J.A1[jz] + (long)row0*KA;
    Bseg[0] = J.B1[jz] + (long)col0*KA;
    Aseg[1] = J.A2[jz] ? (J.A2[jz] + (long)row0*KA) : Aseg[0];
    Bseg[1] = J.B2[jz] ? (J.B2[jz] + (long)col0*KA) : Bseg[0];
    const int SPS = KA / BKs;            /* 24 stages per segment */
    const int S = SPS * J.nseg[jz];

    float acc[2][8][4];
#pragma unroll
    for (int i=0;i<2;i++)
#pragma unroll
        for (int j=0;j<8;j++)
#pragma unroll
            for (int r=0;r<4;r++) acc[i][j][r]=0.f;

    int aM = lane & 15;
    int aK = (lane >> 4) * 8;
    int bN = ((lane >> 4) & 1)*8 + (lane & 7);
    int bK = ((lane >> 3) & 1)*8;

#pragma unroll
    for (int p = 0; p < NSTG-1; p++)
        load_stage(Aseg[0], Bseg[0], p*BKs, sbase + p*STG_BYTES, tid);

    for (int s = 0; s < S; s++){
        cp_wait<NSTG-2>();
        __syncthreads();
        uint32_t sA = sbase + (s % NSTG)*STG_BYTES;
        uint32_t sB = sA + TILE_BYTES;
#pragma unroll
        for (int ks = 0; ks < 2; ks++){
            int k0 = ks*16;
            uint32_t a[2][4];
#pragma unroll
            for (int i=0;i<2;i++){
                uint32_t ad = sA + (uint32_t)(wm*32 + i*16 + aM)*80 + (uint32_t)(k0 + aK)*2;
                ldm_x4(ad, a[i][0], a[i][1], a[i][2], a[i][3]);
            }
            uint32_t b[8][2];
#pragma unroll
            for (int jj=0;jj<4;jj++){
                uint32_t bd = sB + (uint32_t)(wn*64 + jj*16 + bN)*80 + (uint32_t)(k0 + bK)*2;
                uint32_t r0,r1,r2,r3;
                ldm_x4(bd, r0, r1, r2, r3);
                b[2*jj][0]=r0; b[2*jj][1]=r1; b[2*jj+1][0]=r2; b[2*jj+1][1]=r3;
            }
#pragma unroll
            for (int i=0;i<2;i++)
#pragma unroll
                for (int j=0;j<8;j++)
                    mma16816(acc[i][j][0], acc[i][j][1], acc[i][j][2], acc[i][j][3],
                             a[i][0], a[i][1], a[i][2], a[i][3], b[j][0], b[j][1]);
        }
        int nl = s + NSTG - 1;
        if (nl < S){
            int seg = (nl >= SPS) ? 1 : 0;
            int ko  = (nl - seg*SPS) * BKs;
            load_stage(Aseg[seg], Bseg[seg], ko, sbase + (nl % NSTG)*STG_BYTES, tid);
        }
    }

    /* epilogue */
#pragma unroll
    for (int i=0;i<2;i++){
        int rlo = row0 + wm*32 + i*16 + (lane >> 2);
#pragma unroll
        for (int j=0;j<8;j++){
            int c = col0 + wn*64 + j*8 + (lane & 3)*2;
            if (c >= Nout) continue;
#pragma unroll
            for (int h=0;h<2;h++){
                long r = rlo + h*8;
                float v0 = acc[i][j][2*h], v1 = acc[i][j][2*h+1];
                if (bias){ v0 += bias[c]; v1 += bias[c+1]; }
                if (epi == 1 || epi == 5){ v0 = tanhf(v0); v1 = tanhf(v1); }
                else if (epi == 2){
                    __half2 m2 = *(const __half2*)(mult + r*768 + c);
                    v0 = __half2float(m2.x) * sigmoidf_(v0);
                    v1 = __half2float(m2.y) * sigmoidf_(v1);
                }
                if (epi == 0 || epi == 1){
                    float2 st; st.x = v0; st.y = v1;
                    *(float2*)((float*)out + r*(long)Nout + c) = st;
                } else {
                    __half2 hv; hv.x = __float2half(v0); hv.y = __float2half(v1);
                    *(__half2*)((__half*)out + r*(long)Nout + c) = hv;
                }
            }
        }
    }
}

/* ---------------- EMA phase 1 (z-batched jobs) ---------------- */
struct EP {
    const float* in;        /* p1 float input (or null) */
    const __half* inHf;     /* p1 half input (or null) */
    float* h;               /* p1 output / p3 input (chunk-local scan) */
    float* car;             /* carries (raw aggregates) */
    const float* tau;
    const float* cg;        /* optional (p3) */
    const float* delta;     /* optional (p3) */
    __half* outH;           /* p3 fp16 output */
    __half* inH;            /* optional: p1 also emits fp16(in) */
};
struct EPs { EP j[2]; };

__global__ void ema_p1(EPs E)
{
    const EP& e = E.j[blockIdx.z];
    int c  = blockIdx.y*256 + threadIdx.x;
    int b  = blockIdx.x / NCH, ch = blockIdx.x % NCH;
    float alpha = alpha_of(e.tau);
    float*       po = e.h  + ((long)b*Tt + ch*LCH)*Cc + c;
    float h = 0.f;
    if (e.inHf){
        const __half* p = e.inHf + ((long)b*Tt + ch*LCH)*Cc + c;
#pragma unroll 8
        for (int t=0; t<LCH; t++){
            h = fmaf(alpha, h, __half2float(p[(long)t*Cc]));
            po[(long)t*Cc] = h;
        }
    } else if (e.inH){
        const float* p = e.in + ((long)b*Tt + ch*LCH)*Cc + c;
        __half* xo = e.inH + ((long)b*Tt + ch*LCH)*KA + c;
#pragma unroll 8
        for (int t=0; t<LCH; t++){
            float v = p[(long)t*Cc];
            xo[(long)t*KA] = __float2half(v);
            h = fmaf(alpha, h, v);
            po[(long)t*Cc] = h;
        }
    } else {
        const float* p = e.in + ((long)b*Tt + ch*LCH)*Cc + c;
#pragma unroll 8
        for (int t=0; t<LCH; t++){
            h = fmaf(alpha, h, p[(long)t*Cc]);
            po[(long)t*Cc] = h;
        }
    }
    e.car[((long)b*NCH + ch)*Cc + c] = h;
}

/* phase 3 standalone (fast/slow): self-prefix + cg*+delta */
__global__ void ema_p3s(EPs E)
{
    const EP& e = E.j[blockIdx.z];
    int c  = blockIdx.y*256 + threadIdx.x;
    int b  = blockIdx.x / NCH, ch = blockIdx.x % NCH;
    float alpha = alpha_of(e.tau);
    float aL = powf(alpha, (float)LCH);
    const float* carBase = e.car + (long)b*NCH*Cc + c;
    float P = 0.f;
#pragma unroll 8
    for (int j = 0; j < ch; j++)
        P = fmaf(aL, P, carBase[(long)j*Cc]);
    const float* p = e.h + ((long)b*Tt + ch*LCH)*Cc + c;
    const float* cgp = e.cg ? (e.cg + (long)b*Tt + ch*LCH) : nullptr;
    float dl = e.delta ? e.delta[(long)b*Cc + c] : 0.f;
    __half* oH = e.outH + ((long)b*Tt + ch*LCH)*KA + c;
    float ap = alpha;
#pragma unroll 8
    for (int t=0; t<LCH; t++){
        float v = fmaf(ap, P, p[(long)t*Cc]);
        if (cgp) v = fmaf(v, cgp[t], dl);
        oH[(long)t*KA] = __float2half(v);
        ap *= alpha;
    }
}

/* merged: attn partial-max reduce -> cg, and anchor delta */
__global__ void reduce_delta(const float* __restrict__ pm, float* __restrict__ cgout,
                             const float* __restrict__ ancha, const float* __restrict__ scales,
                             float* __restrict__ delta)
{
    int bid = blockIdx.x;
    if (bid < MTOT/256){
        int i = bid*256 + threadIdx.x;
        float m = pm[(long)i*NSB];
#pragma unroll
        for (int j=1;j<NSB;j++) m = fmaxf(m, pm[(long)i*NSB + j]);
        m *= rsqrtf((float)DKk);
        cgout[i] = sigmoidf_(m);
    } else {
        int i = (bid - MTOT/256)*256 + threadIdx.x;
        if (i >= Bb*Cc) return;
        int b = i / Cc, c = i % Cc;
        float s = 0.f;
#pragma unroll
        for (int n=0;n<Nanc;n++){
            float sg = sigmoidf_(scales[n]);
            s += sg * ancha[((long)b*Nanc + n)*Cc + c];
        }
        delta[i] = s;
    }
}

/* ---------------- final gate + layernorm (fp16 inputs) ---------------- */
__global__ void __launch_bounds__(256)
final_k(const __half* __restrict__ gfr, const __half* __restrict__ gsr,
        const __half* __restrict__ somar, const float* __restrict__ blend,
        const float* __restrict__ lng, const float* __restrict__ lnb,
        float* __restrict__ out)
{
    long row = blockIdx.x;
    int tid = threadIdx.x;
    float bl = sigmoidf_(blend[0]);
    float y[3]; float s = 0.f, sq = 0.f;
#pragma unroll
    for (int j=0;j<3;j++){
        int c = tid + j*256;
        long idx = row*Cc + c;
        float f  = sigmoidf_(__half2float(gfr[idx]));
        float g2 = sigmoidf_(__half2float(gsr[idx]));
        float gate = f + bl*(g2 - f);
        float v = tanhf(__half2float(somar[idx])) * gate;
        y[j] = v; s += v; sq += v*v;
    }
    __shared__ float rs[8], rq[8];
#pragma unroll
    for (int o=16;o>0;o>>=1){
        s  += __shfl_xor_sync(0xffffffffu, s,  o);
        sq += __shfl_xor_sync(0xffffffffu, sq, o);
    }
    if ((tid & 31) == 0){ rs[tid>>5] = s; rq[tid>>5] = sq; }
    __syncthreads();
    if (tid == 0){
        float ts=0.f, tq=0.f;
#pragma unroll
        for (int w=0;w<8;w++){ ts += rs[w]; tq += rq[w]; }
        rs[0] = ts; rq[0] = tq;
    }
    __syncthreads();
    float mu  = rs[0] / Cc;
    float var = rq[0] / Cc - mu*mu;
    float inv = rsqrtf(var + 1e-5f);
#pragma unroll
    for (int j=0;j<3;j++){
        int c = tid + j*256;
        long idx = row*Cc + c;
        out[idx] = (y[j]-mu)*inv*lng[c] + lnb[c];
    }
}

/* ---------------- launch ---------------- */
static float* symaddr(const void* sym){
    void* p = nullptr;
    cudaGetSymbolAddress(&p, sym);
    return (float*)p;
}
static __half* symaddrh(const void* sym){
    void* p = nullptr;
    cudaGetSymbolAddress(&p, sym);
    return (__half*)p;
}

extern "C" void kernel_launch(void* const* d_in, const int* in_sizes, int n_in,
                              void* d_out, int out_size)
{
    const float* x        = (const float*)d_in[0];
    const float* tau_gate = (const float*)d_in[1];
    const float* tau_fast = (const float*)d_in[2];
    const float* tau_slow = (const float*)d_in[3];
    const float* Wp   = (const float*)d_in[4];
    const float* bp   = (const float*)d_in[5];
    const float* Wxf  = (const float*)d_in[6];
    const float* bxf  = (const float*)d_in[7];
    const float* Wxs  = (const float*)d_in[8];
    const float* bxs  = (const float*)d_in[9];
    const float* Wcf  = (const float*)d_in[10];
    const float* Wcs  = (const float*)d_in[11];
    const float* Wq   = (const float*)d_in[12];
    const float* Wk   = (const float*)d_in[13];
    const float* Wfast= (const float*)d_in[14];
    const float* bfast= (const float*)d_in[15];
    const float* Wslow= (const float*)d_in[16];
    const float* bslow= (const float*)d_in[17];
    const float* Wsoma= (const float*)d_in[18];
    const float* bsoma= (const float*)d_in[19];
    const float* Wanc = (const float*)d_in[20];
    const float* banc = (const float*)d_in[21];
    const float* ascl = (const float*)d_in[22];
    const float* blend= (const float*)d_in[23];
    const float* lng  = (const float*)d_in[24];
    const float* lnb  = (const float*)d_in[25];
    float* out = (float*)d_out;

    float* ctxg  = symaddr(d_ctxg);
    float* cfF   = symaddr(d_cfF);
    float* csF   = symaddr(d_csF);
    float* pm    = symaddr(d_pm);
    float* cg    = symaddr(d_cg);
    float* anchaF= symaddr(d_anchaF);
    float* delta = symaddr(d_delta);
    float* carG  = symaddr(d_carG);
    float* carF  = symaddr(d_carF);
    float* carS  = symaddr(d_carS);

    __half* xprojH= symaddrh(d_xprojH);
    __half* bfH   = symaddrh(d_bfH);
    __half* bsH   = symaddrh(d_bsH);
    __half* gfrH  = symaddrh(d_gfrH);
    __half* gsrH  = symaddrh(d_gsrH);
    __half* somarH= symaddrh(d_somarH);
    __half* qkH   = symaddrh(d_qkH);
    __half* xaH   = symaddrh(d_xaH);
    __half* xH    = symaddrh(d_xH);
    __half* ctxgH = symaddrh(d_ctxgH);
    __half* cfH   = symaddrh(d_cfH);
    __half* csH   = symaddrh(d_csH);
    __half* WpH   = symaddrh(d_WpH);
    __half* WxfH  = symaddrh(d_WxfH);
    __half* WxsH  = symaddrh(d_WxsH);
    __half* WcfH  = symaddrh(d_WcfH);
    __half* WcsH  = symaddrh(d_WcsH);
    __half* WfastH= symaddrh(d_WfastH);
    __half* WslowH= symaddrh(d_WslowH);
    __half* WsomaH= symaddrh(d_WsomaH);
    __half* WancH = symaddrh(d_WancH);
    __half* WqkH  = symaddrh(d_WqkH);

    cudaFuncSetAttribute(mma_gemm, cudaFuncAttributeMaxDynamicSharedMemorySize, SMEMSZ);

    dim3 gema(Bb*NCH, Cc/256, 1);
    dim3 gema2(Bb*NCH, Cc/256, 2);

    /* 1: anchor rows -> fp16 */
    anchor_gather<<<(Bb*Nanc*Cc+255)/256, 256>>>(x, xaH);

    /* 2: all weight conversions in one launch */
    {
        WConvJobs WJ;
        const float* srcs[11] = {Wp,Wxf,Wxs,Wcf,Wcs,Wfast,Wslow,Wsoma,Wanc,Wq,Wk};
        __half* dsts[11] = {WpH,WxfH,WxsH,WcfH,WcsH,WfastH,WslowH,WsomaH,WancH,
                            WqkH, WqkH + (long)128*KA};
        int ns[11] = {768,768,768,768,768,768,768,768,768,DKk,DKk};
        int np[11] = {768,768,768,768,768,768,768,768,768,128,128};
        for (int i=0;i<11;i++){ WJ.src[i]=srcs[i]; WJ.dst[i]=dsts[i]; WJ.nsrc[i]=ns[i]; WJ.npad[i]=np[i]; }
        conv_w_all<<<dim3(576,11), 256>>>(WJ);
    }

    /* 3: ctx_gate EMA phase 1 on x (also emits xH = fp16(x)) */
    {
        EPs E; E.j[0] = {x, nullptr, ctxg, carG, tau_gate, nullptr, nullptr, ctxgH, xH}; E.j[1] = E.j[0];
        ema_p1<<<gema, 256>>>(E);
    }

    /* 4: batch1 gemm: xproj + qk + anchors + CO-SCHEDULED ctx p3 */
    {
        GemmJobs G = {};
        G.A1[0]=xH;  G.B1[0]=WpH;   G.nseg[0]=1; G.bias[0]=bp;      G.out[0]=xprojH; G.Nout[0]=768; G.ncol[0]=6; G.nrow[0]=64; G.epi[0]=5; G.kind[0]=0;
        G.A1[1]=xH;  G.B1[1]=WqkH;  G.nseg[1]=1; G.bias[1]=nullptr; G.out[1]=qkH;    G.Nout[1]=256; G.ncol[1]=2; G.nrow[1]=64; G.epi[1]=3; G.kind[1]=0;
        G.A1[2]=xaH; G.B1[2]=WancH; G.nseg[2]=1; G.bias[2]=banc;    G.out[2]=anchaF; G.Nout[2]=768; G.ncol[2]=6; G.nrow[2]=1;  G.epi[2]=1; G.kind[2]=0;
        G.kind[3]=2;
        G.e_h = ctxg; G.e_car = carG; G.e_tau = tau_gate; G.e_outH = ctxgH;
        mma_gemm<<<dim3(Bb*NCH*3, 1, 4), 256, SMEMSZ>>>(G);
    }

    /* 5: batch2 gemm: bf, bs + CO-SCHEDULED attention */
    {
        GemmJobs G = {};
        G.A1[0]=xH; G.B1[0]=WxfH; G.A2[0]=ctxgH; G.B2[0]=WcfH; G.nseg[0]=2;
        G.bias[0]=bxf; G.mult[0]=xprojH; G.out[0]=bfH; G.Nout[0]=768; G.ncol[0]=6; G.nrow[0]=64; G.epi[0]=2; G.kind[0]=0;
        G.A1[1]=xH; G.B1[1]=WxsH; G.A2[1]=ctxgH; G.B2[1]=WcsH; G.nseg[1]=2;
        G.bias[1]=bxs; G.mult[1]=xprojH; G.out[1]=bsH; G.Nout[1]=768; G.ncol[1]=6; G.nrow[1]=64; G.epi[1]=2; G.kind[1]=0;
        G.A1[2]=qkH; G.out[2]=pm; G.kind[2]=1;
        G.kind[3]=0; G.ncol[3]=1; G.nrow[3]=0;   /* empty slot */
        mma_gemm<<<dim3(Bb*NT*NSB, 1, 3), 256, SMEMSZ>>>(G);
    }

    /* 6: cg + delta */
    reduce_delta<<<MTOT/256 + (Bb*Cc+255)/256, 256>>>(pm, cg, anchaF, ascl, delta);

    /* 7: fast/slow EMAs: p1 then self-prefix p3 (fused cg*+delta) */
    {
        EPs E;
        E.j[0] = {nullptr, bfH, cfF, carF, tau_fast, cg, delta, cfH, nullptr};
        E.j[1] = {nullptr, bsH, csF, carS, tau_slow, cg, delta, csH, nullptr};
        ema_p1<<<gema2, 256>>>(E);
        ema_p3s<<<gema2, 256>>>(E);
    }

    /* 8: batch3 gemm: gfr, gsr, somar (bias, f16 out) */
    {
        GemmJobs G = {};
        G.A1[0]=cfH; G.B1[0]=WfastH; G.nseg[0]=1; G.bias[0]=bfast; G.out[0]=gfrH;   G.Nout[0]=768; G.ncol[0]=6; G.nrow[0]=64; G.epi[0]=4; G.kind[0]=0;
        G.A1[1]=csH; G.B1[1]=WslowH; G.nseg[1]=1; G.bias[1]=bslow; G.out[1]=gsrH;   G.Nout[1]=768; G.ncol[1]=6; G.nrow[1]=64; G.epi[1]=4; G.kind[1]=0;
        G.A1[2]=xH;  G.B1[2]=WsomaH; G.nseg[2]=1; G.bias[2]=bsoma; G.out[2]=somarH; G.Nout[2]=768; G.ncol[2]=6; G.nrow[2]=64; G.epi[2]=4; G.kind[2]=0;
        mma_gemm<<<dim3(384, 1, 3), 256, SMEMSZ>>>(G);
    }

    /* 9: fused gates + layernorm */
    final_k<<<MTOT, 256>>>(gfrH, gsrH, somarH, blend, lng, lnb, out);
}

// round 15
// speedup vs baseline: 1.0370x; 1.0370x over previous
#include <cuda_runtime.h>
#include <cuda_fp16.h>
#include <cstdint>
#include <math.h>

#define Bb 4
#define Tt 2048
#define Cc 768
#define DKk 96
#define Nanc 8
#define NCH 64
#define LCH 32          /* Tt / NCH */
#define NSB 8
#define NT 16           /* Tt/128 */
#define MTOT (Bb*Tt)    /* 8192 */

#define KA 768          /* fp16 K */
#define BKs 32          /* K per stage */
#define TILE_BYTES (128*40*2)           /* 10240 (row stride 80B) */
#define STG_BYTES (2*TILE_BYTES)        /* A+B per stage: 20480 */
#define NSTG 4
#define SMEMSZ (NSTG*STG_BYTES + 256)   /* 82176 -> 2 CTAs/SM */

#define ATT_STRIDE_B 208                /* 104 halves per row */
#define ATT_TILE_B (128*ATT_STRIDE_B)   /* 26624 */

/* ------------ device scratch (static, no allocation) ------------- */
__device__ float d_ctxg [MTOT*Cc];
__device__ float d_cfF  [MTOT*Cc];
__device__ float d_csF  [MTOT*Cc];
__device__ float d_pm   [MTOT*NSB];
__device__ float d_cg   [MTOT];
__device__ float d_anchaF[128*Cc];
__device__ float d_delta[Bb*Cc];
__device__ float d_carG [Bb*NCH*Cc];
__device__ float d_carF [Bb*NCH*Cc];
__device__ float d_carS [Bb*NCH*Cc];

/* fp16 buffers */
__device__ __half d_xprojH[MTOT*Cc];
__device__ __half d_bfH  [MTOT*Cc];
__device__ __half d_bsH  [MTOT*Cc];
__device__ __half d_gfrH [MTOT*Cc];
__device__ __half d_gsrH [MTOT*Cc];
__device__ __half d_somarH[MTOT*Cc];
__device__ __half d_qkH  [(long)MTOT*256];
__device__ __half d_xaH  [128*KA];
__device__ __half d_xH   [(long)MTOT*KA];
__device__ __half d_ctxgH[(long)MTOT*KA];
__device__ __half d_cfH  [(long)MTOT*KA];
__device__ __half d_csH  [(long)MTOT*KA];
__device__ __half d_WpH   [768*KA];
__device__ __half d_WxfH  [768*KA];
__device__ __half d_WxsH  [768*KA];
__device__ __half d_WcfH  [768*KA];
__device__ __half d_WcsH  [768*KA];
__device__ __half d_WfastH[768*KA];
__device__ __half d_WslowH[768*KA];
__device__ __half d_WsomaH[768*KA];
__device__ __half d_WancH [768*KA];
__device__ __half d_WqkH  [256*KA];

/* ---------------- helpers ---------------- */
__device__ __forceinline__ float alpha_of(const float* tau){
    float t = *tau;
    float sp = (t > 20.f) ? t : log1pf(expf(t));
    return expf(-sp);
}
__device__ __forceinline__ float sigmoidf_(float v){ return 1.f/(1.f+expf(-v)); }

__device__ __forceinline__ uint32_t smem_u32(const void* p){
    uint32_t a;
    asm("{ .reg .u64 t; cvta.to.shared.u64 t, %1; cvt.u32.u64 %0, t; }" : "=r"(a) : "l"(p));
    return a;
}

__device__ __forceinline__ void cp_async16(uint32_t dst, const void* src){
    asm volatile("cp.async.cg.shared.global [%0], [%1], 16;" :: "r"(dst), "l"(src));
}
__device__ __forceinline__ void cp_commit(){ asm volatile("cp.async.commit_group;" ::: "memory"); }
template<int N> __device__ __forceinline__ void cp_wait(){ asm volatile("cp.async.wait_group %0;" :: "n"(N) : "memory"); }

__device__ __forceinline__ void ldm_x4(uint32_t addr, uint32_t& r0, uint32_t& r1, uint32_t& r2, uint32_t& r3){
    asm volatile("ldmatrix.sync.aligned.m8n8.x4.shared.b16 {%0,%1,%2,%3}, [%4];"
        : "=r"(r0), "=r"(r1), "=r"(r2), "=r"(r3) : "r"(addr));
}
__device__ __forceinline__ void mma16816(float& c0, float& c1, float& c2, float& c3,
                                         uint32_t a0, uint32_t a1, uint32_t a2, uint32_t a3,
                                         uint32_t b0, uint32_t b1){
    asm volatile("mma.sync.aligned.m16n8k16.row.col.f32.f16.f16.f32 "
        "{%0,%1,%2,%3}, {%4,%5,%6,%7}, {%8,%9}, {%0,%1,%2,%3};"
        : "+f"(c0), "+f"(c1), "+f"(c2), "+f"(c3)
        : "r"(a0), "r"(a1), "r"(a2), "r"(a3), "r"(b0), "r"(b1));
}

/* ---------------- fp16 conversion kernels (weights + anchor gather) -------- */
struct WConvJobs {
    const float* src[11];
    __half* dst[11];
    int nsrc[11];
    int npad[11];
    const float* x;         /* for anchor gather (y == 11) */
    __half* xa;
};
__global__ void conv_w_all(WConvJobs J)
{
    int j = blockIdx.y;
    if (j == 11){
        int i = blockIdx.x*256 + threadIdx.x;
        if (i >= Bb*Nanc*Cc) return;
        int c = i % Cc;
        int n = (i / Cc) % Nanc;
        int b = i / (Cc*Nanc);
        int pos = n * (Tt / Nanc);
        if (pos > Tt-1) pos = Tt-1;
        J.xa[i] = __float2half(J.x[((long)b*Tt + pos)*Cc + c]);
        return;
    }
    long i = (long)blockIdx.x*256 + threadIdx.x;
    int npad = J.npad[j];
    if (i >= (long)npad*192) return;
    int r = (int)(i / 192); int c4 = (int)(i % 192);
    float4 v = make_float4(0.f,0.f,0.f,0.f);
    if (r < J.nsrc[j]) v = *(const float4*)(J.src[j] + (long)r*768 + c4*4);
    __half2 a; a.x=__float2half(v.x); a.y=__float2half(v.y);
    __half2 b; b.x=__float2half(v.z); b.y=__float2half(v.w);
    __half2* o = (__half2*)(J.dst[j] + (long)r*KA + c4*4);
    o[0]=a; o[1]=b;
}

/* ---------------- batched mma.sync GEMM + co-scheduled attention ----------
   per z-job, kind 0: out[nrow*128, Nout] = epi( sum_seg A_seg@B_seg^T + bias )
   kind 1: causal max attention (A1 = qk, out = pm)
   epi: 0 f32, 1 tanh f32, 2 sigmoid*multH f16, 3 f16, 4 f16, 5 tanh f16 */
struct GemmJobs {
    const __half *A1[3], *B1[3], *A2[3], *B2[3];
    const float *bias[3];
    const __half *mult[3];
    void *out[3];
    int nseg[3], Nout[3], ncol[3], nrow[3], epi[3], kind[3];
};

__device__ __forceinline__ void load_stage(const __half* __restrict__ A,
                                           const __half* __restrict__ Bp,
                                           int kofs, uint32_t sbuf, int tid)
{
    uint32_t sA = sbuf, sB = sbuf + TILE_BYTES;
#pragma unroll
    for (int it = 0; it < 2; it++){
        int ci = it*256 + tid;
        int row = ci >> 2, c = ci & 3;
        cp_async16(sA + row*80 + c*16, A + (long)row*KA + kofs + c*8);
    }
#pragma unroll
    for (int it = 0; it < 2; it++){
        int ci = it*256 + tid;
        int row = ci >> 2, c = ci & 3;
        cp_async16(sB + row*80 + c*16, Bp + (long)row*KA + kofs + c*8);
    }
    cp_commit();
}

/* attention body (flattened blockIdx.x over Bb*NT*NSB) */
__device__ void attn_body(const __half* __restrict__ qk, float* __restrict__ pm,
                          char* dynA)
{
    int idx = blockIdx.x;
    if (idx >= Bb*NT*NSB) return;
    int sb  = idx % NSB;
    int btt = idx / NSB;
    int b = btt / NT, tt = btt % NT;
    __half* qs = (__half*)dynA;
    __half* ks = (__half*)(dynA + ATT_TILE_B);
    int tid = threadIdx.x, lane = tid & 31, wid = tid >> 5;
    int wm = wid & 3, wn = wid >> 2;
    uint32_t sq = smem_u32(qs), sk = smem_u32(ks);

    const __half* qbase = qk + ((long)b*Tt + tt*128)*256;
    for (int ch = tid; ch < 128*12; ch += 256){
        int row = ch / 12, cc = ch % 12;
        cp_async16(sq + row*208 + cc*16, qbase + (long)row*256 + cc*8);
    }
    cp_commit(); cp_wait<0>(); __syncthreads();

    int aM = lane & 15, aK = (lane >> 4)*8;
    int bN = ((lane >> 4) & 1)*8 + (lane & 7), bK = ((lane >> 3) & 1)*8;

    float mreg[2][2];
    mreg[0][0]=mreg[0][1]=mreg[1][0]=mreg[1][1] = -INFINITY;

    for (int st = sb; st <= tt; st += NSB){
        const __half* kbase = qk + ((long)b*Tt + st*128)*256 + 128;
        for (int ch = tid; ch < 128*12; ch += 256){
            int row = ch / 12, cc = ch % 12;
            cp_async16(sk + row*208 + cc*16, kbase + (long)row*256 + cc*8);
        }
        cp_commit(); cp_wait<0>(); __syncthreads();

        float acc[2][8][4];
#pragma unroll
        for (int i=0;i<2;i++)
#pragma unroll
            for (int j=0;j<8;j++)
#pragma unroll
                for (int r=0;r<4;r++) acc[i][j][r]=0.f;

#pragma unroll
        for (int kk=0; kk<6; kk++){
            int k0 = kk*16;
            uint32_t a[2][4];
#pragma unroll
            for (int i=0;i<2;i++){
                uint32_t ad = sq + (uint32_t)(wm*32 + i*16 + aM)*208 + (uint32_t)(k0 + aK)*2;
                ldm_x4(ad, a[i][0], a[i][1], a[i][2], a[i][3]);
            }
            uint32_t bfr[8][2];
#pragma unroll
            for (int jj=0;jj<4;jj++){
                uint32_t bd = sk + (uint32_t)(wn*64 + jj*16 + bN)*208 + (uint32_t)(k0 + bK)*2;
                uint32_t r0,r1,r2,r3;
                ldm_x4(bd, r0, r1, r2, r3);
                bfr[2*jj][0]=r0; bfr[2*jj][1]=r1; bfr[2*jj+1][0]=r2; bfr[2*jj+1][1]=r3;
            }
#pragma unroll
            for (int i=0;i<2;i++)
#pragma unroll
                for (int j=0;j<8;j++)
                    mma16816(acc[i][j][0], acc[i][j][1], acc[i][j][2], acc[i][j][3],
                             a[i][0], a[i][1], a[i][2], a[i][3], bfr[j][0], bfr[j][1]);
        }
        __syncthreads();

        bool diag = (st == tt);
#pragma unroll
        for (int i=0;i<2;i++)
#pragma unroll
            for (int j=0;j<8;j++)
#pragma unroll
                for (int h=0;h<2;h++){
                    float v0 = acc[i][j][2*h], v1 = acc[i][j][2*h+1];
                    if (diag){
                        int row = wm*32 + i*16 + h*8 + (lane >> 2);
                        int col = wn*64 + j*8 + (lane & 3)*2;
                        if (col     > row) v0 = -INFINITY;
                        if (col + 1 > row) v1 = -INFINITY;
                    }
                    mreg[i][h] = fmaxf(mreg[i][h], fmaxf(v0, v1));
                }
    }

#pragma unroll
    for (int i=0;i<2;i++)
#pragma unroll
        for (int h=0;h<2;h++){
            float v = mreg[i][h];
            v = fmaxf(v, __shfl_xor_sync(0xffffffffu, v, 1));
            v = fmaxf(v, __shfl_xor_sync(0xffffffffu, v, 2));
            mreg[i][h] = v;
        }
    float* red = (float*)qs;
    __syncthreads();
    if ((lane & 3) == 0){
#pragma unroll
        for (int i=0;i<2;i++)
#pragma unroll
            for (int h=0;h<2;h++){
                int rowl = wm*32 + i*16 + h*8 + (lane >> 2);
                red[wn*128 + rowl] = mreg[i][h];
            }
    }
    __syncthreads();
    if (tid < 128){
        float v = fmaxf(red[tid], red[128 + tid]);
        pm[((long)b*Tt + tt*128 + tid)*NSB + sb] = v;
    }
}

__global__ void __launch_bounds__(256, 2)
mma_gemm(GemmJobs J)
{
    extern __shared__ char dyn[];
    const int jz = blockIdx.z;
    if (J.kind[jz] == 1){
        attn_body(J.A1[jz], (float*)J.out[jz], dyn);
        return;
    }
    const int ncol = J.ncol[jz];
    const int bx = blockIdx.x;
    if (bx >= ncol * J.nrow[jz]) return;
    const int tid  = threadIdx.x;
    const int lane = tid & 31;
    const int wid  = tid >> 5;
    const int wm   = wid & 3;
    const int wn   = wid >> 2;
    const int row0 = (bx / ncol) * 128;
    const int col0 = (bx % ncol) * 128;
    const int Nout = J.Nout[jz];
    const int epi  = J.epi[jz];
    const float* bias = J.bias[jz];
    const __half* mult = J.mult[jz];
    void* out = J.out[jz];
    uint32_t sbase = (smem_u32(dyn) + 127u) & ~127u;

    const __half* Aseg[2];
    const __half* Bseg[2];
    Aseg[0] = J.A1[jz] + (long)row0*KA;
    Bseg[0] = J.B1[jz] + (long)col0*KA;
    Aseg[1] = J.A2[jz] ? (J.A2[jz] + (long)row0*KA) : Aseg[0];
    Bseg[1] = J.B2[jz] ? (J.B2[jz] + (long)col0*KA) : Bseg[0];
    const int SPS = KA / BKs;            /* 24 stages per segment */
    const int S = SPS * J.nseg[jz];

    float acc[2][8][4];
#pragma unroll
    for (int i=0;i<2;i++)
#pragma unroll
        for (int j=0;j<8;j++)
#pragma unroll
            for (int r=0;r<4;r++) acc[i][j][r]=0.f;

    int aM = lane & 15;
    int aK = (lane >> 4) * 8;
    int bN = ((lane >> 4) & 1)*8 + (lane & 7);
    int bK = ((lane >> 3) & 1)*8;

#pragma unroll
    for (int p = 0; p < NSTG-1; p++)
        load_stage(Aseg[0], Bseg[0], p*BKs, sbase + p*STG_BYTES, tid);

    for (int s = 0; s < S; s++){
        cp_wait<NSTG-2>();
        __syncthreads();
        uint32_t sA = sbase + (s % NSTG)*STG_BYTES;
        uint32_t sB = sA + TILE_BYTES;
#pragma unroll
        for (int ks = 0; ks < 2; ks++){
            int k0 = ks*16;
            uint32_t a[2][4];
#pragma unroll
            for (int i=0;i<2;i++){
                uint32_t ad = sA + (uint32_t)(wm*32 + i*16 + aM)*80 + (uint32_t)(k0 + aK)*2;
                ldm_x4(ad, a[i][0], a[i][1], a[i][2], a[i][3]);
            }
            uint32_t b[8][2];
#pragma unroll
            for (int jj=0;jj<4;jj++){
                uint32_t bd = sB + (uint32_t)(wn*64 + jj*16 + bN)*80 + (uint32_t)(k0 + bK)*2;
                uint32_t r0,r1,r2,r3;
                ldm_x4(bd, r0, r1, r2, r3);
                b[2*jj][0]=r0; b[2*jj][1]=r1; b[2*jj+1][0]=r2; b[2*jj+1][1]=r3;
            }
#pragma unroll
            for (int i=0;i<2;i++)
#pragma unroll
                for (int j=0;j<8;j++)
                    mma16816(acc[i][j][0], acc[i][j][1], acc[i][j][2], acc[i][j][3],
                             a[i][0], a[i][1], a[i][2], a[i][3], b[j][0], b[j][1]);
        }
        int nl = s + NSTG - 1;
        if (nl < S){
            int seg = (nl >= SPS) ? 1 : 0;
            int ko  = (nl - seg*SPS) * BKs;
            load_stage(Aseg[seg], Bseg[seg], ko, sbase + (nl % NSTG)*STG_BYTES, tid);
        }
    }

    /* epilogue */
#pragma unroll
    for (int i=0;i<2;i++){
        int rlo = row0 + wm*32 + i*16 + (lane >> 2);
#pragma unroll
        for (int j=0;j<8;j++){
            int c = col0 + wn*64 + j*8 + (lane & 3)*2;
            if (c >= Nout) continue;
#pragma unroll
            for (int h=0;h<2;h++){
                long r = rlo + h*8;
                float v0 = acc[i][j][2*h], v1 = acc[i][j][2*h+1];
                if (bias){ v0 += bias[c]; v1 += bias[c+1]; }
                if (epi == 1 || epi == 5){ v0 = tanhf(v0); v1 = tanhf(v1); }
                else if (epi == 2){
                    __half2 m2 = *(const __half2*)(mult + r*768 + c);
                    v0 = __half2float(m2.x) * sigmoidf_(v0);
                    v1 = __half2float(m2.y) * sigmoidf_(v1);
                }
                if (epi == 0 || epi == 1){
                    float2 st; st.x = v0; st.y = v1;
                    *(float2*)((float*)out + r*(long)Nout + c) = st;
                } else {
                    __half2 hv; hv.x = __float2half(v0); hv.y = __float2half(v1);
                    *(__half2*)((__half*)out + r*(long)Nout + c) = hv;
                }
            }
        }
    }
}

/* ---------------- EMA: 3-phase chunked scan (z-batched jobs) ---------------- */
struct EP {
    const float* in;        /* p1 float input (or null) */
    const __half* inHf;     /* p1 half input (or null) */
    float* h;               /* p1 output / p3 input (chunk-local scan) */
    float* car;             /* carries */
    const float* tau;
    const float* cg;        /* optional */
    const float* delta;     /* optional */
    __half* outH;           /* p3 fp16 output */
    __half* inH;            /* optional: p1 also emits fp16(in) */
};
struct EPs { EP j[2]; };

__device__ void ema_p1_body(const EP& e)
{
    int c  = blockIdx.y*256 + threadIdx.x;
    int b  = blockIdx.x / NCH, ch = blockIdx.x % NCH;
    float alpha = alpha_of(e.tau);
    float*       po = e.h  + ((long)b*Tt + ch*LCH)*Cc + c;
    float h = 0.f;
    if (e.inHf){
        const __half* p = e.inHf + ((long)b*Tt + ch*LCH)*Cc + c;
#pragma unroll 8
        for (int t=0; t<LCH; t++){
            h = fmaf(alpha, h, __half2float(p[(long)t*Cc]));
            po[(long)t*Cc] = h;
        }
    } else if (e.inH){
        const float* p = e.in + ((long)b*Tt + ch*LCH)*Cc + c;
        __half* xo = e.inH + ((long)b*Tt + ch*LCH)*KA + c;
#pragma unroll 8
        for (int t=0; t<LCH; t++){
            float v = p[(long)t*Cc];
            xo[(long)t*KA] = __float2half(v);
            h = fmaf(alpha, h, v);
            po[(long)t*Cc] = h;
        }
    } else {
        const float* p = e.in + ((long)b*Tt + ch*LCH)*Cc + c;
#pragma unroll 8
        for (int t=0; t<LCH; t++){
            h = fmaf(alpha, h, p[(long)t*Cc]);
            po[(long)t*Cc] = h;
        }
    }
    e.car[((long)b*NCH + ch)*Cc + c] = h;
}

__global__ void ema_p1(EPs E)
{
    ema_p1_body(E.j[blockIdx.z]);
}

/* combined: fast/slow ema p1 (z 0,1) + reduce_delta (z 2) */
struct EP1RD {
    EP j[2];
    const float* pm; float* cgout;
    const float* ancha; const float* scales; float* delta;
};
__global__ void ema_p1_rd(EP1RD E)
{
    if (blockIdx.z < 2){ ema_p1_body(E.j[blockIdx.z]); return; }
    int flat = blockIdx.x*3 + blockIdx.y;
    if (flat < MTOT/256){
        int i = flat*256 + threadIdx.x;
        float m = E.pm[(long)i*NSB];
#pragma unroll
        for (int j=1;j<NSB;j++) m = fmaxf(m, E.pm[(long)i*NSB + j]);
        m *= rsqrtf((float)DKk);
        E.cgout[i] = sigmoidf_(m);
    } else if (flat < MTOT/256 + (Bb*Cc+255)/256){
        int i = (flat - MTOT/256)*256 + threadIdx.x;
        if (i >= Bb*Cc) return;
        int b = i / Cc, c = i % Cc;
        float s = 0.f;
#pragma unroll
        for (int n=0;n<Nanc;n++){
            float sg = sigmoidf_(E.scales[n]);
            s += sg * E.ancha[((long)b*Nanc + n)*Cc + c];
        }
        E.delta[i] = s;
    }
}

/* phase 2: register-buffered exclusive prefix over chunk carries */
__global__ void ema_p2(EPs E)
{
    const EP& e = E.j[blockIdx.z];
    int i = blockIdx.x*256 + threadIdx.x;
    if (i >= Bb*Cc) return;
    int b = i / Cc, c = i % Cc;
    float alpha = alpha_of(e.tau);
    float aL = powf(alpha, (float)LCH);
    float* base = e.car + (long)b*NCH*Cc + c;
    float vb[NCH];
#pragma unroll
    for (int ch=0; ch<NCH; ch++) vb[ch] = base[(long)ch*Cc];
    float H = 0.f;
#pragma unroll
    for (int ch=0; ch<NCH; ch++){
        float cv = vb[ch];
        base[(long)ch*Cc] = H;
        H = fmaf(aL, H, cv);
    }
}

/* phase 3: inject carry, apply optional cg*+delta, emit fp16 */
__global__ void ema_p3s(EPs E)
{
    const EP& e = E.j[blockIdx.z];
    int c  = blockIdx.y*256 + threadIdx.x;
    int b  = blockIdx.x / NCH, ch = blockIdx.x % NCH;
    float alpha = alpha_of(e.tau);
    float P = e.car[((long)b*NCH+ch)*Cc + c];
    const float* p = e.h + ((long)b*Tt + ch*LCH)*Cc + c;
    const float* cgp = e.cg ? (e.cg + (long)b*Tt + ch*LCH) : nullptr;
    float dl = e.delta ? e.delta[(long)b*Cc + c] : 0.f;
    __half* oH = e.outH + ((long)b*Tt + ch*LCH)*KA + c;
    float ap = alpha;
#pragma unroll 8
    for (int t=0; t<LCH; t++){
        float v = fmaf(ap, P, p[(long)t*Cc]);
        if (cgp) v = fmaf(v, cgp[t], dl);
        oH[(long)t*KA] = __float2half(v);
        ap *= alpha;
    }
}

/* ---------------- final gate + layernorm (fp16 inputs) ---------------- */
__global__ void __launch_bounds__(256)
final_k(const __half* __restrict__ gfr, const __half* __restrict__ gsr,
        const __half* __restrict__ somar, const float* __restrict__ blend,
        const float* __restrict__ lng, const float* __restrict__ lnb,
        float* __restrict__ out)
{
    long row = blockIdx.x;
    int tid = threadIdx.x;
    float bl = sigmoidf_(blend[0]);
    float y[3]; float s = 0.f, sq = 0.f;
#pragma unroll
    for (int j=0;j<3;j++){
        int c = tid + j*256;
        long idx = row*Cc + c;
        float f  = sigmoidf_(__half2float(gfr[idx]));
        float g2 = sigmoidf_(__half2float(gsr[idx]));
        float gate = f + bl*(g2 - f);
        float v = tanhf(__half2float(somar[idx])) * gate;
        y[j] = v; s += v; sq += v*v;
    }
    __shared__ float rs[8], rq[8];
#pragma unroll
    for (int o=16;o>0;o>>=1){
        s  += __shfl_xor_sync(0xffffffffu, s,  o);
        sq += __shfl_xor_sync(0xffffffffu, sq, o);
    }
    if ((tid & 31) == 0){ rs[tid>>5] = s; rq[tid>>5] = sq; }
    __syncthreads();
    if (tid == 0){
        float ts=0.f, tq=0.f;
#pragma unroll
        for (int w=0;w<8;w++){ ts += rs[w]; tq += rq[w]; }
        rs[0] = ts; rq[0] = tq;
    }
    __syncthreads();
    float mu  = rs[0] / Cc;
    float var = rq[0] / Cc - mu*mu;
    float inv = rsqrtf(var + 1e-5f);
#pragma unroll
    for (int j=0;j<3;j++){
        int c = tid + j*256;
        long idx = row*Cc + c;
        out[idx] = (y[j]-mu)*inv*lng[c] + lnb[c];
    }
}

/* ---------------- launch ---------------- */
static float* symaddr(const void* sym){
    void* p = nullptr;
    cudaGetSymbolAddress(&p, sym);
    return (float*)p;
}
static __half* symaddrh(const void* sym){
    void* p = nullptr;
    cudaGetSymbolAddress(&p, sym);
    return (__half*)p;
}

extern "C" void kernel_launch(void* const* d_in, const int* in_sizes, int n_in,
                              void* d_out, int out_size)
{
    const float* x        = (const float*)d_in[0];
    const float* tau_gate = (const float*)d_in[1];
    const float* tau_fast = (const float*)d_in[2];
    const float* tau_slow = (const float*)d_in[3];
    const float* Wp   = (const float*)d_in[4];
    const float* bp   = (const float*)d_in[5];
    const float* Wxf  = (const float*)d_in[6];
    const float* bxf  = (const float*)d_in[7];
    const float* Wxs  = (const float*)d_in[8];
    const float* bxs  = (const float*)d_in[9];
    const float* Wcf  = (const float*)d_in[10];
    const float* Wcs  = (const float*)d_in[11];
    const float* Wq   = (const float*)d_in[12];
    const float* Wk   = (const float*)d_in[13];
    const float* Wfast= (const float*)d_in[14];
    const float* bfast= (const float*)d_in[15];
    const float* Wslow= (const float*)d_in[16];
    const float* bslow= (const float*)d_in[17];
    const float* Wsoma= (const float*)d_in[18];
    const float* bsoma= (const float*)d_in[19];
    const float* Wanc = (const float*)d_in[20];
    const float* banc = (const float*)d_in[21];
    const float* ascl = (const float*)d_in[22];
    const float* blend= (const float*)d_in[23];
    const float* lng  = (const float*)d_in[24];
    const float* lnb  = (const float*)d_in[25];
    float* out = (float*)d_out;

    float* ctxg  = symaddr(d_ctxg);
    float* cfF   = symaddr(d_cfF);
    float* csF   = symaddr(d_csF);
    float* pm    = symaddr(d_pm);
    float* cg    = symaddr(d_cg);
    float* anchaF= symaddr(d_anchaF);
    float* delta = symaddr(d_delta);
    float* carG  = symaddr(d_carG);
    float* carF  = symaddr(d_carF);
    float* carS  = symaddr(d_carS);

    __half* xprojH= symaddrh(d_xprojH);
    __half* bfH   = symaddrh(d_bfH);
    __half* bsH   = symaddrh(d_bsH);
    __half* gfrH  = symaddrh(d_gfrH);
    __half* gsrH  = symaddrh(d_gsrH);
    __half* somarH= symaddrh(d_somarH);
    __half* qkH   = symaddrh(d_qkH);
    __half* xaH   = symaddrh(d_xaH);
    __half* xH    = symaddrh(d_xH);
    __half* ctxgH = symaddrh(d_ctxgH);
    __half* cfH   = symaddrh(d_cfH);
    __half* csH   = symaddrh(d_csH);
    __half* WpH   = symaddrh(d_WpH);
    __half* WxfH  = symaddrh(d_WxfH);
    __half* WxsH  = symaddrh(d_WxsH);
    __half* WcfH  = symaddrh(d_WcfH);
    __half* WcsH  = symaddrh(d_WcsH);
    __half* WfastH= symaddrh(d_WfastH);
    __half* WslowH= symaddrh(d_WslowH);
    __half* WsomaH= symaddrh(d_WsomaH);
    __half* WancH = symaddrh(d_WancH);
    __half* WqkH  = symaddrh(d_WqkH);

    cudaFuncSetAttribute(mma_gemm, cudaFuncAttributeMaxDynamicSharedMemorySize, SMEMSZ);

    dim3 gema(Bb*NCH, Cc/256, 1);
    dim3 gema2(Bb*NCH, Cc/256, 2);

    /* 1: all weight conversions + anchor gather in one launch */
    {
        WConvJobs WJ;
        const float* srcs[11] = {Wp,Wxf,Wxs,Wcf,Wcs,Wfast,Wslow,Wsoma,Wanc,Wq,Wk};
        __half* dsts[11] = {WpH,WxfH,WxsH,WcfH,WcsH,WfastH,WslowH,WsomaH,WancH,
                            WqkH, WqkH + (long)128*KA};
        int ns[11] = {768,768,768,768,768,768,768,768,768,DKk,DKk};
        int np[11] = {768,768,768,768,768,768,768,768,768,128,128};
        for (int i=0;i<11;i++){ WJ.src[i]=srcs[i]; WJ.dst[i]=dsts[i]; WJ.nsrc[i]=ns[i]; WJ.npad[i]=np[i]; }
        WJ.x = x; WJ.xa = xaH;
        conv_w_all<<<dim3(576,12), 256>>>(WJ);
    }

    /* 2: ctx_gate EMA on x -> ctxgH; p1 also emits xH = fp16(x) */
    {
        EPs E; E.j[0] = {x, nullptr, ctxg, carG, tau_gate, nullptr, nullptr, ctxgH, xH}; E.j[1] = E.j[0];
        ema_p1<<<gema, 256>>>(E);
        ema_p2<<<dim3((Bb*Cc+255)/256,1,1), 256>>>(E);
        ema_p3s<<<gema, 256>>>(E);
    }

    /* 3: batch1 gemm: xproj (tanh,f16) + qk (f16) + anchors (tanh,f32) */
    {
        GemmJobs G = {};
        G.A1[0]=xH;  G.B1[0]=WpH;   G.nseg[0]=1; G.bias[0]=bp;      G.out[0]=xprojH; G.Nout[0]=768; G.ncol[0]=6; G.nrow[0]=64; G.epi[0]=5; G.kind[0]=0;
        G.A1[1]=xH;  G.B1[1]=WqkH;  G.nseg[1]=1; G.bias[1]=nullptr; G.out[1]=qkH;    G.Nout[1]=256; G.ncol[1]=2; G.nrow[1]=64; G.epi[1]=3; G.kind[1]=0;
        G.A1[2]=xaH; G.B1[2]=WancH; G.nseg[2]=1; G.bias[2]=banc;    G.out[2]=anchaF; G.Nout[2]=768; G.ncol[2]=6; G.nrow[2]=1;  G.epi[2]=1; G.kind[2]=0;
        mma_gemm<<<dim3(384, 1, 3), 256, SMEMSZ>>>(G);
    }

    /* 4: batch2 gemm: bf, bs (sigmoid * xprojH, f16 out) + CO-SCHEDULED attention */
    {
        GemmJobs G = {};
        G.A1[0]=xH; G.B1[0]=WxfH; G.A2[0]=ctxgH; G.B2[0]=WcfH; G.nseg[0]=2;
        G.bias[0]=bxf; G.mult[0]=xprojH; G.out[0]=bfH; G.Nout[0]=768; G.ncol[0]=6; G.nrow[0]=64; G.epi[0]=2; G.kind[0]=0;
        G.A1[1]=xH; G.B1[1]=WxsH; G.A2[1]=ctxgH; G.B2[1]=WcsH; G.nseg[1]=2;
        G.bias[1]=bxs; G.mult[1]=xprojH; G.out[1]=bsH; G.Nout[1]=768; G.ncol[1]=6; G.nrow[1]=64; G.epi[1]=2; G.kind[1]=0;
        G.A1[2]=qkH; G.out[2]=pm; G.kind[2]=1;
        mma_gemm<<<dim3(Bb*NT*NSB, 1, 3), 256, SMEMSZ>>>(G);
    }

    /* 5: fast/slow ema p1 + merged reduce_delta (independent, same frontier) */
    {
        EP1RD E;
        E.j[0] = {nullptr, bfH, cfF, carF, tau_fast, cg, delta, cfH, nullptr};
        E.j[1] = {nullptr, bsH, csF, carS, tau_slow, cg, delta, csH, nullptr};
        E.pm = pm; E.cgout = cg; E.ancha = anchaF; E.scales = ascl; E.delta = delta;
        ema_p1_rd<<<dim3(Bb*NCH, Cc/256, 3), 256>>>(E);
    }

    /* 6: fast/slow p2 + p3 (fused cg*+delta, f16 out) */
    {
        EPs E;
        E.j[0] = {nullptr, bfH, cfF, carF, tau_fast, cg, delta, cfH, nullptr};
        E.j[1] = {nullptr, bsH, csF, carS, tau_slow, cg, delta, csH, nullptr};
        ema_p2<<<dim3((Bb*Cc+255)/256,1,2), 256>>>(E);
        ema_p3s<<<gema2, 256>>>(E);
    }

    /* 7: batch3 gemm: gfr, gsr, somar (bias, f16 out) */
    {
        GemmJobs G = {};
        G.A1[0]=cfH; G.B1[0]=WfastH; G.nseg[0]=1; G.bias[0]=bfast; G.out[0]=gfrH;   G.Nout[0]=768; G.ncol[0]=6; G.nrow[0]=64; G.epi[0]=4; G.kind[0]=0;
        G.A1[1]=csH; G.B1[1]=WslowH; G.nseg[1]=1; G.bias[1]=bslow; G.out[1]=gsrH;   G.Nout[1]=768; G.ncol[1]=6; G.nrow[1]=64; G.epi[1]=4; G.kind[1]=0;
        G.A1[2]=xH;  G.B1[2]=WsomaH; G.nseg[2]=1; G.bias[2]=bsoma; G.out[2]=somarH; G.Nout[2]=768; G.ncol[2]=6; G.nrow[2]=64; G.epi[2]=4; G.kind[2]=0;
        mma_gemm<<<dim3(384, 1, 3), 256, SMEMSZ>>>(G);
    }

    /* 8: fused gates + layernorm */
    final_k<<<MTOT, 256>>>(gfrH, gsrH, somarH, blend, lng, lnb, out);
}